// round 17
// baseline (speedup 1.0000x reference)
#include <cuda_runtime.h>

// DTW 65536 x 512 — 4 CTAs x 128 threads, 1 column/thread, R=32 rows/tick.
// R15 = R10 trunk (measured-best config) + two instruction cuts:
//   * producer-side pre-min handoff: pm[r] = min(ev[r-1], ev[r]) computed in
//     the producer's chain-stall shadow and shfl'd; the consumer uses it
//     directly as m = min(diag,left) — deletes the consumer's 32-fmin pass
//     and dlast tracking. g_edge / lbuf / eb all carry pm.
//   * the 32-shfl block moves to the iteration tail (after pm, before the
//     barrier) so shfl latency overlaps barrier arrival spread.

#define N_ROWS  65536
#define NCTA    4
#define NTHR    128
#define NWARP   4
#define R       32
#define NTICK   (N_ROWS / R)          // 2048
#define NITER   (NTICK + NTHR - 1)    // 2175
#define CHUNK   32                    // ticks per cross-CTA chunk
#define XSTRIDE 36                    // floats per ring slot (32 data + 4 pad)

__device__ __align__(16) float g_edge[NCTA - 1][N_ROWS];
__device__ int g_flag[NCTA - 1];

__global__ void dtw_init_flags()
{
    if (threadIdx.x < NCTA - 1) g_flag[threadIdx.x] = 0;
}

__device__ __forceinline__ int flag_acquire(const int* p)
{
    int v;
    asm volatile("ld.acquire.gpu.global.b32 %0, [%1];" : "=r"(v) : "l"(p) : "memory");
    return v;
}

__device__ __forceinline__ void flag_release(int* p, int v)
{
    asm volatile("st.release.gpu.global.b32 [%0], %1;" :: "l"(p), "r"(v) : "memory");
}

__global__ __launch_bounds__(NTHR, 1)
void dtw_pm32_kernel(const float* __restrict__ x,
                     const float* __restrict__ kern,
                     float* __restrict__ out)
{
    __shared__ __align__(16) float s_xring[NWARP][64 * XSTRIDE]; // 36 KB x rings
    __shared__ __align__(16) float lbuf[2][CHUNK * R];           // 8 KB cross-CTA pm staging
    __shared__ __align__(16) float eb[2][NWARP - 1][R];          // warp-boundary pm

    const int   c   = (int)blockIdx.x;
    const int   tid = (int)threadIdx.x;
    const int   w   = tid >> 5;
    const int   l   = tid & 31;
    const float INF = __int_as_float(0x7f800000);

    const float kv    = kern[c * NTHR + tid];
    const bool  pred0 = (c == 0) && (tid == 0);
    const bool  wout  = (c == NCTA - 1) && (tid == NTHR - 1);
    float* const myring = s_xring[w];

    // ---- initial x ring fill: ticks [-32w-31, -32w+32], 2 slots per lane ----
    #pragma unroll
    for (int k2 = 0; k2 < 2; ++k2) {
        const int T  = -32 * w - 31 + l + 32 * k2;
        const int Tc = min(max(T, 0), NTICK - 1);
        const float4* xp = (const float4*)(x + Tc * R);
        float4* dst = (float4*)&myring[(((unsigned)T) & 63u) * XSTRIDE];
        #pragma unroll
        for (int q = 0; q < 8; ++q) dst[q] = xp[q];
    }

    // ---- init warp-boundary buffers (hygiene) ----
    for (int k2 = tid; k2 < 2 * (NWARP - 1) * R; k2 += NTHR)
        ((float*)eb)[k2] = INF;

    // ---- prestage chunk 0 of the left-CTA boundary (pm values) ----
    if (c == 0) {
        #pragma unroll
        for (int k2 = 0; k2 < (2 * CHUNK * R) / NTHR; ++k2)
            lbuf[0][tid + NTHR * k2] = INF;       // both buffers: never restaged
    } else {
        if (tid == 0) {
            while (flag_acquire(&g_flag[c - 1]) < CHUNK) { }
        }
        __syncthreads();
        #pragma unroll
        for (int k2 = 0; k2 < 2; ++k2)
            *(float4*)&lbuf[0][4 * (2 * tid + k2)] =
                __ldcg((const float4*)g_edge[c - 1] + 2 * tid + k2);
    }
    __syncthreads();

    float L[R], pm[R];
    #pragma unroll
    for (int r = 0; r < R; ++r) { L[r] = INF; pm[r] = INF; }
    float vlast = INF;                  // own previous active tick's ev[R-1]

    for (int i = 0; i < NITER; ++i) {
        // ---- every 32 iters: refill my ring + cross-CTA chunk staging ----
        if ((i & (CHUNK - 1)) == 0) {
            {
                const int T  = i - 32 * w + l;
                const int Tc = min(max(T, 0), NTICK - 1);
                const float4* xp = (const float4*)(x + Tc * R);
                float4* dst = (float4*)&myring[(((unsigned)T) & 63u) * XSTRIDE];
                #pragma unroll
                for (int q = 0; q < 8; ++q) dst[q] = xp[q];
            }
            if (c > 0) {
                const int base = i + CHUNK;
                if (base < NTICK) {
                    if (tid == 0) {
                        const int need = min(base + CHUNK, NTICK);
                        while (flag_acquire(&g_flag[c - 1]) < need) { }
                    }
                    __syncthreads();
                    const int buf = ((i >> 5) + 1) & 1;
                    #pragma unroll
                    for (int k2 = 0; k2 < 2; ++k2)
                        *(float4*)&lbuf[buf][4 * (2 * tid + k2)] =
                            __ldcg((const float4*)(g_edge[c - 1] + base * R) + 2 * tid + k2);
                    // consumed >= 32 iterations later; per-iteration barrier
                    // below orders these STS before those reads.
                }
            }
        }

        // ---- lane-0 boundary source (warp-uniform branch, broadcast LDS) ----
        {
            const float* src = (w == 0)
                ? &lbuf[(i >> 5) & 1][(i & (CHUNK - 1)) * R]
                : &eb[(i & 1) ^ 1][w - 1][0];
            #pragma unroll
            for (int h = 0; h < 8; ++h) {
                const float4 a = ((const float4*)src)[h];
                L[4*h]   = (l == 0) ? a.x : L[4*h];
                L[4*h+1] = (l == 0) ? a.y : L[4*h+1];
                L[4*h+2] = (l == 0) ? a.z : L[4*h+2];
                L[4*h+3] = (l == 0) ? a.w : L[4*h+3];
            }
        }
        // virtual 0 at (row 0, col -1): left-use only, at cell (0,0)
        L[0] = (pred0 && i == 0) ? 0.0f : L[0];

        const int  t      = i - tid;
        const bool active = (t >= 0) && (t < NTICK);
        const bool do_out = wout && active;

        // ---- chain: min-plus prefix + producer-side pre-min, ev rolling ----
        // q = L[r]-S; S = fma(ts,ts,S); cm = min(cm,q); ev = S+cm; pm = min(ep,ev)
        const float4* sp4 = (const float4*)&myring[(((unsigned)t) & 63u) * XSTRIDE];
        float S, cm, ep;
        float4 v4;
        {
            const float4 xa = sp4[0];
            const float tt = kv - xa.x;
            S  = tt * tt;
            cm = fminf(vlast, L[0]);
            ep = S + cm;                 // ev[0]
            pm[0] = fminf(vlast, ep);
            v4.x = ep;
            #pragma unroll
            for (int r = 1; r < 4; ++r) {
                const float t2 = kv - ((const float*)&xa)[r];
                const float q  = L[r] - S;
                S  = fmaf(t2, t2, S);
                cm = fminf(cm, q);
                const float e = S + cm;
                pm[r] = fminf(ep, e);
                ((float*)&v4)[r] = e;
                ep = e;
            }
            if (do_out) ((float4*)(out + t * R))[0] = v4;
        }
        #pragma unroll
        for (int h = 1; h < 8; ++h) {
            const float4 xa = sp4[h];
            #pragma unroll
            for (int r = 0; r < 4; ++r) {
                const float t2 = kv - ((const float*)&xa)[r];
                const float q  = L[4*h + r] - S;
                S  = fmaf(t2, t2, S);
                cm = fminf(cm, q);
                const float e = S + cm;
                pm[4*h + r] = fminf(ep, e);
                ((float*)&v4)[r] = e;
                ep = e;
            }
            if (do_out) ((float4*)(out + t * R))[h] = v4;
        }
        vlast = active ? ep : vlast;

        // ---- publish pm: warp boundary via smem, CTA boundary via global ----
        if (l == 31) {
            if (w < NWARP - 1) {
                float4* d = (float4*)&eb[i & 1][w][0];
                #pragma unroll
                for (int q = 0; q < 8; ++q)
                    d[q] = make_float4(pm[4*q], pm[4*q+1], pm[4*q+2], pm[4*q+3]);
            } else if (active && c < NCTA - 1) {
                float4* ep4 = (float4*)(g_edge[c] + t * R);
                #pragma unroll
                for (int q = 0; q < 8; ++q)
                    ep4[q] = make_float4(pm[4*q], pm[4*q+1], pm[4*q+2], pm[4*q+3]);
                if ((t & 7) == 7)
                    flag_release(&g_flag[c], t + 1);
            }
        }

        // ---- shfl for NEXT iteration, in the barrier's shadow ----
        #pragma unroll
        for (int r = 0; r < R; ++r)
            L[r] = __shfl_up_sync(0xffffffffu, pm[r], 1);

        __syncthreads();
    }
}

extern "C" void kernel_launch(void* const* d_in, const int* in_sizes, int n_in,
                              void* d_out, int out_size)
{
    const float* x = (const float*)d_in[0];   // input  [65536]
    const float* k = (const float*)d_in[1];   // kernel [512]
    float* out = (float*)d_out;               // [65536] float32

    dtw_init_flags<<<1, 32>>>();
    dtw_pm32_kernel<<<NCTA, NTHR>>>(x, k, out);
}